// round 8
// baseline (speedup 1.0000x reference)
#include <cuda_runtime.h>
#include <cuda_fp16.h>
#include <cstdint>

// ColBERT MaxSim on GB300 (sm_103): barrier-free warp-private pipelines.
// Each warp owns a 256-token slice of the doc, all 4 queries (M=128), private
// cp.async double buffer. No __syncthreads in the main loop.
// qs: (64, 32, 128) fp32 ; ps: (64, 1024, 128) fp32 ; out: (64, 64) fp32

#define NQ       64
#define TQ       32
#define ND       64
#define TS       1024
#define DIM      128
#define G_Q      4                     // queries per CTA
#define THREADS  128
#define NT       32                    // tokens per chunk (per warp)
#define NCH      8                     // chunks per warp slice (256 tokens)
#define ROWB     256                   // bytes per token/A row in smem
#define ABYTES   (128 * ROWB)          // 32 KB  (A: 128 rows x 128 f16)
#define BBUF     (NT * ROWB)           // 8 KB per buffer
#define SMEM_A   0
#define SMEM_B   ABYTES                // 4 warps x 2 bufs x 8KB = 64 KB
#define SMEM_RED (SMEM_B + 4 * 2 * BBUF)
#define SMEM_TOT (SMEM_RED + 4 * 128 * 4)
#define U_TOK    (DIM / 8)             // uint4 units per token row = 16

// fp16 scratch (device-global; allocation-free per harness rules)
__device__ uint4 scratch_ps_v[(size_t)ND * TS * DIM / 8];   // 16 MB
__device__ uint4 scratch_qs_v[(size_t)NQ * TQ * DIM / 8];   // 512 KB

__global__ void cvt_ps_kernel(const float4* __restrict__ src) {
    int i = blockIdx.x * blockDim.x + threadIdx.x;
    float4 a = src[2 * i], b = src[2 * i + 1];
    uint4 o; __half2 h;
    h = __floats2half2_rn(a.x, a.y); o.x = *reinterpret_cast<uint32_t*>(&h);
    h = __floats2half2_rn(a.z, a.w); o.y = *reinterpret_cast<uint32_t*>(&h);
    h = __floats2half2_rn(b.x, b.y); o.z = *reinterpret_cast<uint32_t*>(&h);
    h = __floats2half2_rn(b.z, b.w); o.w = *reinterpret_cast<uint32_t*>(&h);
    scratch_ps_v[i] = o;
}
__global__ void cvt_qs_kernel(const float4* __restrict__ src) {
    int i = blockIdx.x * blockDim.x + threadIdx.x;
    float4 a = src[2 * i], b = src[2 * i + 1];
    uint4 o; __half2 h;
    h = __floats2half2_rn(a.x, a.y); o.x = *reinterpret_cast<uint32_t*>(&h);
    h = __floats2half2_rn(a.z, a.w); o.y = *reinterpret_cast<uint32_t*>(&h);
    h = __floats2half2_rn(b.x, b.y); o.z = *reinterpret_cast<uint32_t*>(&h);
    h = __floats2half2_rn(b.z, b.w); o.w = *reinterpret_cast<uint32_t*>(&h);
    scratch_qs_v[i] = o;
}

__device__ __forceinline__ uint32_t smem_u32(const void* p) {
    uint32_t a;
    asm("{ .reg .u64 t; cvta.to.shared.u64 t, %1; cvt.u32.u64 %0, t; }" : "=r"(a) : "l"(p));
    return a;
}
// m16n8k16 f16 in / f16 acc
__device__ __forceinline__ void mma_f16acc(unsigned& d0, unsigned& d1,
                                           unsigned a0, unsigned a1, unsigned a2, unsigned a3,
                                           unsigned b0, unsigned b1) {
    asm volatile(
        "mma.sync.aligned.m16n8k16.row.col.f16.f16.f16.f16 "
        "{%0,%1}, {%2,%3,%4,%5}, {%6,%7}, {%0,%1};\n"
        : "+r"(d0), "+r"(d1)
        : "r"(a0), "r"(a1), "r"(a2), "r"(a3), "r"(b0), "r"(b1));
}
__device__ __forceinline__ unsigned hmax2_u(unsigned a, unsigned b) {
    __half2 r = __hmax2(*reinterpret_cast<__half2*>(&a), *reinterpret_cast<__half2*>(&b));
    return *reinterpret_cast<unsigned*>(&r);
}
__device__ __forceinline__ float hmax_final(unsigned a) {
    __half2 h = *reinterpret_cast<__half2*>(&a);
    return fmaxf(__low2float(h), __high2float(h));
}

__global__ __launch_bounds__(THREADS, 2)
void colbert_kernel(float* __restrict__ out) {
    extern __shared__ __align__(1024) char smem[];
    const uint32_t sb = smem_u32(smem);

    const int tid   = threadIdx.x;
    const int w     = tid >> 5;
    const int lane  = tid & 31;
    const int g     = lane >> 2;       // mma row within 8
    const int t     = lane & 3;        // mma col pair
    const int c_doc = blockIdx.x;
    const int qg    = blockIdx.y;

    // per-warp doc-slice base: token index (c_doc*TS + w*256), 16 uint4 units per token
    const uint4* gsrc = scratch_ps_v + ((size_t)c_doc * TS + (size_t)w * 256) * U_TOK;

    // ---- prologue: cp.async A (whole CTA) + B chunk 0 (per warp) ----
    {
        const uint4* aq = scratch_qs_v + (size_t)qg * 128 * U_TOK;
        #pragma unroll
        for (int i = 0; i < 16; i++) {
            int f = i * THREADS + tid;            // 2048 16B units
            int r = f >> 4, u = f & 15;
            uint32_t dst = sb + SMEM_A + r * ROWB + ((u ^ (r & 7)) << 4);
            asm volatile("cp.async.cg.shared.global [%0], [%1], 16;\n" :: "r"(dst), "l"(aq + f));
        }
        uint32_t bbase = sb + SMEM_B + w * 2 * BBUF;
        #pragma unroll
        for (int i = 0; i < 16; i++) {
            int f = i * 32 + lane;                // 512 units (32 tokens)
            int r = f >> 4, u = f & 15;
            uint32_t dst = bbase + r * ROWB + ((u ^ (r & 7)) << 4);
            asm volatile("cp.async.cg.shared.global [%0], [%1], 16;\n" :: "r"(dst), "l"(gsrc + f));
        }
        asm volatile("cp.async.commit_group;\n");
        asm volatile("cp.async.wait_group 0;\n");
    }
    __syncthreads();   // A visible to all warps; only barrier before epilogue

    // packed running maxes per m-tile: [mt][0]=row mt*16+g, [mt][1]=row mt*16+8+g (cols 2t,2t+1)
    unsigned rmax[8][2];
    #pragma unroll
    for (int mt = 0; mt < 8; mt++) { rmax[mt][0] = 0xFC00FC00u; rmax[mt][1] = 0xFC00FC00u; }

    const int rl = lane & 7;            // B: token row within 8
    const int mc = lane >> 3;           // B: matrix select
    const int ar = lane & 15;           // A: row within 16
    const int asel = lane >> 4;         // A: k-half select
    const uint32_t Ab = sb + SMEM_A;
    const uint32_t Bw = sb + SMEM_B + w * 2 * BBUF;

    #pragma unroll 1
    for (int ch = 0; ch < NCH; ch++) {
        // issue next chunk into other buffer (warp-private, no barrier)
        if (ch + 1 < NCH) {
            const uint4* gs2 = gsrc + (size_t)(ch + 1) * NT * U_TOK;
            uint32_t dbuf = Bw + ((ch + 1) & 1) * BBUF;
            #pragma unroll
            for (int i = 0; i < 16; i++) {
                int f = i * 32 + lane;
                int r = f >> 4, u = f & 15;
                uint32_t dst = dbuf + r * ROWB + ((u ^ (r & 7)) << 4);
                asm volatile("cp.async.cg.shared.global [%0], [%1], 16;\n" :: "r"(dst), "l"(gs2 + f));
            }
            asm volatile("cp.async.commit_group;\n");
        }

        // ---- B fragments for this chunk: 4 n-frags x full k128 ----
        const uint32_t cb = Bw + (ch & 1) * BBUF;
        unsigned B[4][4][4];   // [nf][j(k32 quad)][reg]
        #pragma unroll
        for (int nf = 0; nf < 4; nf++) {
            uint32_t nb = cb + nf * 8 * ROWB + rl * ROWB;
            #pragma unroll
            for (int j = 0; j < 4; j++) {
                uint32_t addr = nb + ((((j << 2) | mc) ^ rl) << 4);
                asm volatile("ldmatrix.sync.aligned.m8n8.x4.shared.b16 {%0,%1,%2,%3}, [%4];\n"
                             : "=r"(B[nf][j][0]), "=r"(B[nf][j][1]),
                               "=r"(B[nf][j][2]), "=r"(B[nf][j][3]) : "r"(addr));
            }
        }

        // ---- per m-tile: load A frags, 4 independent acc chains (nf) ----
        #pragma unroll
        for (int mt = 0; mt < 8; mt++) {
            unsigned A[8][4];
            const int arow = mt * 16 + ar;
            const uint32_t abase = Ab + arow * ROWB;
            #pragma unroll
            for (int s = 0; s < 8; s++) {
                uint32_t u = 2 * s + asel;
                uint32_t addr = abase + ((u ^ (arow & 7)) << 4);
                asm volatile("ldmatrix.sync.aligned.m8n8.x4.shared.b16 {%0,%1,%2,%3}, [%4];\n"
                             : "=r"(A[s][0]), "=r"(A[s][1]), "=r"(A[s][2]), "=r"(A[s][3])
                             : "r"(addr));
            }
            unsigned d[4][2] = {{0,0},{0,0},{0,0},{0,0}};
            #pragma unroll
            for (int s = 0; s < 8; s++) {
                #pragma unroll
                for (int nf = 0; nf < 4; nf++) {
                    unsigned b0 = B[nf][s >> 1][(s & 1) * 2];
                    unsigned b1 = B[nf][s >> 1][(s & 1) * 2 + 1];
                    mma_f16acc(d[nf][0], d[nf][1],
                               A[s][0], A[s][1], A[s][2], A[s][3], b0, b1);
                }
            }
            // fold the 4 token-groups into running maxes
            unsigned m0 = hmax2_u(hmax2_u(d[0][0], d[1][0]), hmax2_u(d[2][0], d[3][0]));
            unsigned m1 = hmax2_u(hmax2_u(d[0][1], d[1][1]), hmax2_u(d[2][1], d[3][1]));
            rmax[mt][0] = hmax2_u(rmax[mt][0], m0);
            rmax[mt][1] = hmax2_u(rmax[mt][1], m1);
        }

        if (ch + 1 < NCH) {
            asm volatile("cp.async.wait_group 0;\n");
            __syncwarp();
        }
    }

    // ---- per-warp partial row maxes -> smem ----
    float* red = reinterpret_cast<float*>(smem + SMEM_RED);
    #pragma unroll
    for (int mt = 0; mt < 8; mt++) {
        unsigned u0 = rmax[mt][0], u1 = rmax[mt][1];
        #pragma unroll
        for (int off = 1; off <= 2; off <<= 1) {
            u0 = hmax2_u(u0, __shfl_xor_sync(0xffffffffu, u0, off));
            u1 = hmax2_u(u1, __shfl_xor_sync(0xffffffffu, u1, off));
        }
        if (t == 0) {
            red[w * 128 + mt * 16 + g]     = hmax_final(u0);
            red[w * 128 + mt * 16 + 8 + g] = hmax_final(u1);
        }
    }
    __syncthreads();

    // ---- final: row r = tid; combine 4 warps, sum 32 tokens per query ----
    {
        float v = fmaxf(fmaxf(red[tid], red[128 + tid]),
                        fmaxf(red[256 + tid], red[384 + tid]));
        #pragma unroll
        for (int off = 16; off >= 1; off >>= 1)
            v += __shfl_xor_sync(0xffffffffu, v, off);
        if (lane == 0) out[(qg * G_Q + w) * ND + c_doc] = v;
    }
}

extern "C" void kernel_launch(void* const* d_in, const int* in_sizes, int n_in,
                              void* d_out, int out_size) {
    const float* qs = (const float*)d_in[0];   // 64*32*128
    const float* ps = (const float*)d_in[1];   // 64*1024*128
    float* out = (float*)d_out;                // 64*64

    cudaFuncSetAttribute(colbert_kernel, cudaFuncAttributeMaxDynamicSharedMemorySize, SMEM_TOT);

    cvt_ps_kernel<<<(ND * TS * DIM / 8) / 256, 256>>>((const float4*)ps);
    cvt_qs_kernel<<<(NQ * TQ * DIM / 8) / 256, 256>>>((const float4*)qs);

    dim3 grid(ND, NQ / G_Q);                   // (64 docs, 16 query groups)
    colbert_kernel<<<grid, THREADS, SMEM_TOT>>>(out);
}

// round 9
// speedup vs baseline: 1.2653x; 1.2653x over previous
#include <cuda_runtime.h>
#include <cuda_fp16.h>
#include <cstdint>

// ColBERT MaxSim on GB300 (sm_103): R4 core + balanced persistent partition.
// 592 CTAs (one full wave), chunk-granular static work split, atomicMax combine.
// qs: (64, 32, 128) fp32 ; ps: (64, 1024, 128) fp32 ; out: (64, 64) fp32

#define NQ       64
#define TQ       32
#define ND       64
#define TS       1024
#define DIM      128
#define G_Q      4
#define THREADS  128
#define SN       64                    // doc tokens per chunk
#define CPS      16                    // chunks per segment (1024/64)
#define NSEG     (ND * (NQ / G_Q))     // 1024 segments (doc x qg)
#define TOTU     (NSEG * CPS)          // 16384 chunk units
#define NCTA     592                   // 148 SMs x 4 CTAs
#define BIGCTAS  400                   // 400*28 + 192*27 = 16384
#define ROWB     256
#define BUFB     (SN * ROWB)           // 16 KB
#define U_TOK    (DIM / 8)             // uint4 per token row

// fp16 ps scratch + max staging (device-global; allocation-free)
__device__ uint4 scratch_ps_v[(size_t)ND * TS * DIM / 8];   // 16 MB
__device__ unsigned g_stage[NSEG * 128];                    // 512 KB

#define ENC_NEGINF 0x007FFFFFu   // enc(-inf)

__device__ __forceinline__ unsigned enc_f(float f) {
    unsigned u = __float_as_uint(f);
    return (u & 0x80000000u) ? ~u : (u | 0x80000000u);
}
__device__ __forceinline__ float dec_f(unsigned k) {
    unsigned u = (k & 0x80000000u) ? (k & 0x7FFFFFFFu) : ~k;
    return __uint_as_float(u);
}

__global__ void cvt_ps_kernel(const float4* __restrict__ src) {
    int i = blockIdx.x * blockDim.x + threadIdx.x;
    float4 a = src[2 * i], b = src[2 * i + 1];
    uint4 o; __half2 h;
    h = __floats2half2_rn(a.x, a.y); o.x = *reinterpret_cast<uint32_t*>(&h);
    h = __floats2half2_rn(a.z, a.w); o.y = *reinterpret_cast<uint32_t*>(&h);
    h = __floats2half2_rn(b.x, b.y); o.z = *reinterpret_cast<uint32_t*>(&h);
    h = __floats2half2_rn(b.z, b.w); o.w = *reinterpret_cast<uint32_t*>(&h);
    scratch_ps_v[i] = o;
}

__global__ void init_stage_kernel() {
    int i = blockIdx.x * blockDim.x + threadIdx.x;
    g_stage[i] = ENC_NEGINF;
}

__global__ void final_kernel(float* __restrict__ out) {
    int j = blockIdx.x * blockDim.x + threadIdx.x;   // 4096
    int b = j >> 6, c = j & 63;                      // query, doc
    int qg = b >> 2, wq = b & 3;
    const unsigned* s = g_stage + ((size_t)(qg * ND + c)) * 128 + wq * 32;
    float v = 0.f;
    #pragma unroll
    for (int tok = 0; tok < 32; tok++) v += dec_f(s[tok]);
    out[b * ND + c] = v;
}

__device__ __forceinline__ uint32_t smem_u32(const void* p) {
    uint32_t a;
    asm("{ .reg .u64 t; cvta.to.shared.u64 t, %1; cvt.u32.u64 %0, t; }" : "=r"(a) : "l"(p));
    return a;
}
__device__ __forceinline__ unsigned pack_h2(float lo, float hi) {
    __half2 h = __floats2half2_rn(lo, hi);
    return *reinterpret_cast<unsigned*>(&h);
}
__device__ __forceinline__ void mma_f16(float c[4],
                                        unsigned a0, unsigned a1, unsigned a2, unsigned a3,
                                        unsigned b0, unsigned b1) {
    asm volatile(
        "mma.sync.aligned.m16n8k16.row.col.f32.f16.f16.f32 "
        "{%0,%1,%2,%3}, {%4,%5,%6,%7}, {%8,%9}, {%0,%1,%2,%3};\n"
        : "+f"(c[0]), "+f"(c[1]), "+f"(c[2]), "+f"(c[3])
        : "r"(a0), "r"(a1), "r"(a2), "r"(a3), "r"(b0), "r"(b1));
}

__global__ __launch_bounds__(THREADS, 4)
void colbert_kernel(const float* __restrict__ qs) {
    __shared__ __align__(1024) char Bs[2 * BUFB];

    const int tid   = threadIdx.x;
    const int w     = tid >> 5;
    const int lane  = tid & 31;
    const int g     = lane >> 2;
    const int t     = lane & 3;
    const uint32_t sb = smem_u32(Bs);
    const int rl = lane & 7;
    const int mc = lane >> 3;

    // balanced static partition of chunk units
    const int bid = blockIdx.x;
    int u  = (bid < BIGCTAS) ? bid * 28 : BIGCTAS * 28 + (bid - BIGCTAS) * 27;
    const int u1 = u + ((bid < BIGCTAS) ? 28 : 27);

    unsigned Af[2][8][4];
    int prev_qg = -1;

    #pragma unroll 1
    while (u < u1) {
        const int seg  = u >> 4;          // seg = qg*64 + doc
        const int qg   = seg >> 6;
        const int doc  = seg & 63;
        const int c0   = u & 15;
        const int cend = min(u1 - (seg << 4), CPS);

        const uint4* gsrc = scratch_ps_v + (size_t)doc * TS * U_TOK;

        __syncthreads();   // prior segment's readers done before buf0 overwrite

        // prologue: chunk c0 -> buffer 0
        {
            const uint4* bq = gsrc + (size_t)c0 * SN * U_TOK;
            #pragma unroll
            for (int j = 0; j < 8; j++) {
                int f = j * THREADS + tid;
                int r = f >> 4, cc = f & 15;
                uint32_t dst = sb + r * ROWB + ((cc ^ (r & 7)) << 4);
                asm volatile("cp.async.cg.shared.global [%0], [%1], 16;\n" :: "r"(dst), "l"(bq + f));
            }
            asm volatile("cp.async.commit_group;\n");
        }

        // A fragments (reload only when query group changes)
        if (qg != prev_qg) {
            prev_qg = qg;
            const int rbase = (qg * G_Q + w) * TQ;
            #pragma unroll
            for (int mt = 0; mt < 2; mt++) {
                #pragma unroll
                for (int ks = 0; ks < 8; ks++) {
                    const int r0 = rbase + mt * 16 + g;
                    const int cc = ks * 16 + t * 2;
                    const float2* p0 = reinterpret_cast<const float2*>(qs + (size_t)r0 * DIM + cc);
                    const float2* p1 = reinterpret_cast<const float2*>(qs + (size_t)(r0 + 8) * DIM + cc);
                    float2 v00 = p0[0];
                    float2 v02 = p0[4];
                    float2 v10 = p1[0];
                    float2 v12 = p1[4];
                    Af[mt][ks][0] = pack_h2(v00.x, v00.y);
                    Af[mt][ks][1] = pack_h2(v10.x, v10.y);
                    Af[mt][ks][2] = pack_h2(v02.x, v02.y);
                    Af[mt][ks][3] = pack_h2(v12.x, v12.y);
                }
            }
        }

        float rmax0 = -1e30f, rmax1 = -1e30f, rmax2 = -1e30f, rmax3 = -1e30f;

        #pragma unroll 1
        for (int c = c0; c < cend; c++) {
            const int lc = c - c0;
            asm volatile("cp.async.wait_group 0;\n");
            __syncthreads();

            if (c + 1 < cend) {
                const uint4* gs2  = gsrc + (size_t)(c + 1) * SN * U_TOK;
                uint32_t     dbuf = sb + ((lc + 1) & 1) * BUFB;
                #pragma unroll
                for (int j = 0; j < 8; j++) {
                    int f = j * THREADS + tid;
                    int r = f >> 4, cc = f & 15;
                    uint32_t dst = dbuf + r * ROWB + ((cc ^ (r & 7)) << 4);
                    asm volatile("cp.async.cg.shared.global [%0], [%1], 16;\n" :: "r"(dst), "l"(gs2 + f));
                }
                asm volatile("cp.async.commit_group;\n");
            }

            const uint32_t cbase = sb + (lc & 1) * BUFB + rl * ROWB;
            #pragma unroll
            for (int nf = 0; nf < 8; nf++) {
                float cA[4] = {0.f, 0.f, 0.f, 0.f};
                float cB[4] = {0.f, 0.f, 0.f, 0.f};
                #pragma unroll
                for (int kp = 0; kp < 4; kp++) {
                    uint32_t addr = cbase + nf * 8 * ROWB + ((((kp << 2) | mc) ^ rl) << 4);
                    uint32_t b0, b1, b2, b3;
                    asm volatile("ldmatrix.sync.aligned.m8n8.x4.shared.b16 {%0,%1,%2,%3}, [%4];\n"
                                 : "=r"(b0), "=r"(b1), "=r"(b2), "=r"(b3) : "r"(addr));
                    mma_f16(cA, Af[0][2*kp][0],   Af[0][2*kp][1],   Af[0][2*kp][2],   Af[0][2*kp][3],   b0, b1);
                    mma_f16(cB, Af[1][2*kp][0],   Af[1][2*kp][1],   Af[1][2*kp][2],   Af[1][2*kp][3],   b0, b1);
                    mma_f16(cA, Af[0][2*kp+1][0], Af[0][2*kp+1][1], Af[0][2*kp+1][2], Af[0][2*kp+1][3], b2, b3);
                    mma_f16(cB, Af[1][2*kp+1][0], Af[1][2*kp+1][1], Af[1][2*kp+1][2], Af[1][2*kp+1][3], b2, b3);
                }
                rmax0 = fmaxf(rmax0, fmaxf(cA[0], cA[1]));
                rmax1 = fmaxf(rmax1, fmaxf(cA[2], cA[3]));
                rmax2 = fmaxf(rmax2, fmaxf(cB[0], cB[1]));
                rmax3 = fmaxf(rmax3, fmaxf(cB[2], cB[3]));
            }
        }

        // complete row maxes across the 4 lanes sharing g, then combine globally
        #pragma unroll
        for (int off = 1; off <= 2; off <<= 1) {
            rmax0 = fmaxf(rmax0, __shfl_xor_sync(0xffffffffu, rmax0, off));
            rmax1 = fmaxf(rmax1, __shfl_xor_sync(0xffffffffu, rmax1, off));
            rmax2 = fmaxf(rmax2, __shfl_xor_sync(0xffffffffu, rmax2, off));
            rmax3 = fmaxf(rmax3, __shfl_xor_sync(0xffffffffu, rmax3, off));
        }
        if (t == 0) {
            unsigned* s = g_stage + (size_t)seg * 128 + w * 32;
            atomicMax(&s[g],      enc_f(rmax0));
            atomicMax(&s[g + 8],  enc_f(rmax1));
            atomicMax(&s[g + 16], enc_f(rmax2));
            atomicMax(&s[g + 24], enc_f(rmax3));
        }

        u = (seg << 4) + cend;
    }
}

extern "C" void kernel_launch(void* const* d_in, const int* in_sizes, int n_in,
                              void* d_out, int out_size) {
    const float* qs = (const float*)d_in[0];   // 64*32*128
    const float* ps = (const float*)d_in[1];   // 64*1024*128
    float* out = (float*)d_out;                // 64*64

    cvt_ps_kernel<<<(ND * TS * DIM / 8) / 256, 256>>>((const float4*)ps);
    init_stage_kernel<<<(NSEG * 128) / 256, 256>>>();
    colbert_kernel<<<NCTA, THREADS>>>(qs);
    final_kernel<<<(NQ * ND) / 256, 256>>>(out);
}

// round 10
// speedup vs baseline: 1.2898x; 1.0194x over previous
#include <cuda_runtime.h>
#include <cuda_fp16.h>
#include <cstdint>

// ColBERT MaxSim on GB300 (sm_103): balanced persistent main (R8) + slim overheads.
// 592 CTAs (one wave), chunk-granular static split, atomicMax combine.
// qs: (64, 32, 128) fp32 ; ps: (64, 1024, 128) fp32 ; out: (64, 64) fp32

#define NQ       64
#define TQ       32
#define ND       64
#define TS       1024
#define DIM      128
#define G_Q      4
#define THREADS  128
#define SN       64                    // doc tokens per chunk
#define CPS      16                    // chunks per segment (1024/64)
#define NSEG     (ND * (NQ / G_Q))     // 1024 segments (qg x doc)
#define TOTU     (NSEG * CPS)          // 16384 chunk units
#define NCTA     592                   // 148 SMs x 4 CTAs
#define BIGCTAS  400                   // 400*28 + 192*27 = 16384
#define ROWB     256
#define BUFB     (SN * ROWB)           // 16 KB
#define U_TOK    (DIM / 8)             // uint4 per token row

// fp16 ps scratch + max staging (device-global; allocation-free)
__device__ uint4 scratch_ps_v[(size_t)ND * TS * DIM / 8];   // 16 MB
__device__ unsigned g_stage[NSEG * 128];                    // 512 KB

#define ENC_NEGINF 0x007FFFFFu   // enc(-inf)

__device__ __forceinline__ unsigned enc_f(float f) {
    unsigned u = __float_as_uint(f);
    return (u & 0x80000000u) ? ~u : (u | 0x80000000u);
}
__device__ __forceinline__ float dec_f(unsigned k) {
    unsigned u = (k & 0x80000000u) ? (k & 0x7FFFFFFFu) : ~k;
    return __uint_as_float(u);
}

// fp32->fp16 convert (x2 per thread, MLP=4) + staging init folded in
__global__ void cvt_ps_kernel(const float4* __restrict__ src) {
    int i = blockIdx.x * blockDim.x + threadIdx.x;    // 524288 threads
    float4 a0 = src[4 * i],     a1 = src[4 * i + 1];
    float4 b0 = src[4 * i + 2], b1 = src[4 * i + 3];
    uint4 o0, o1; __half2 h;
    h = __floats2half2_rn(a0.x, a0.y); o0.x = *reinterpret_cast<uint32_t*>(&h);
    h = __floats2half2_rn(a0.z, a0.w); o0.y = *reinterpret_cast<uint32_t*>(&h);
    h = __floats2half2_rn(a1.x, a1.y); o0.z = *reinterpret_cast<uint32_t*>(&h);
    h = __floats2half2_rn(a1.z, a1.w); o0.w = *reinterpret_cast<uint32_t*>(&h);
    h = __floats2half2_rn(b0.x, b0.y); o1.x = *reinterpret_cast<uint32_t*>(&h);
    h = __floats2half2_rn(b0.z, b0.w); o1.y = *reinterpret_cast<uint32_t*>(&h);
    h = __floats2half2_rn(b1.x, b1.y); o1.z = *reinterpret_cast<uint32_t*>(&h);
    h = __floats2half2_rn(b1.z, b1.w); o1.w = *reinterpret_cast<uint32_t*>(&h);
    scratch_ps_v[2 * i]     = o0;
    scratch_ps_v[2 * i + 1] = o1;
    if (i < NSEG * 128) g_stage[i] = ENC_NEGINF;      // init staging, no extra launch
}

// one warp per (query, doc): lane = token, 1 load + warp sum
__global__ void final_kernel(float* __restrict__ out) {
    int wrp  = (blockIdx.x * blockDim.x + threadIdx.x) >> 5;   // 0..4095
    int lane = threadIdx.x & 31;
    int b = wrp >> 6, c = wrp & 63;                 // query, doc
    int qg = b >> 2, wq = b & 3;
    float v = dec_f(g_stage[((size_t)(qg * ND + c)) * 128 + wq * 32 + lane]);
    #pragma unroll
    for (int off = 16; off >= 1; off >>= 1)
        v += __shfl_xor_sync(0xffffffffu, v, off);
    if (lane == 0) out[b * ND + c] = v;
}

__device__ __forceinline__ uint32_t smem_u32(const void* p) {
    uint32_t a;
    asm("{ .reg .u64 t; cvta.to.shared.u64 t, %1; cvt.u32.u64 %0, t; }" : "=r"(a) : "l"(p));
    return a;
}
__device__ __forceinline__ unsigned pack_h2(float lo, float hi) {
    __half2 h = __floats2half2_rn(lo, hi);
    return *reinterpret_cast<unsigned*>(&h);
}
__device__ __forceinline__ void mma_f16(float c[4],
                                        unsigned a0, unsigned a1, unsigned a2, unsigned a3,
                                        unsigned b0, unsigned b1) {
    asm volatile(
        "mma.sync.aligned.m16n8k16.row.col.f32.f16.f16.f32 "
        "{%0,%1,%2,%3}, {%4,%5,%6,%7}, {%8,%9}, {%0,%1,%2,%3};\n"
        : "+f"(c[0]), "+f"(c[1]), "+f"(c[2]), "+f"(c[3])
        : "r"(a0), "r"(a1), "r"(a2), "r"(a3), "r"(b0), "r"(b1));
}

__global__ __launch_bounds__(THREADS, 4)
void colbert_kernel(const float* __restrict__ qs) {
    __shared__ __align__(1024) char Bs[2 * BUFB];

    const int tid   = threadIdx.x;
    const int w     = tid >> 5;
    const int lane  = tid & 31;
    const int g     = lane >> 2;
    const int t     = lane & 3;
    const uint32_t sb = smem_u32(Bs);
    const int rl = lane & 7;
    const int mc = lane >> 3;

    // balanced static partition of chunk units
    const int bid = blockIdx.x;
    int u  = (bid < BIGCTAS) ? bid * 28 : BIGCTAS * 28 + (bid - BIGCTAS) * 27;
    const int u1 = u + ((bid < BIGCTAS) ? 28 : 27);

    unsigned Af[2][8][4];
    int prev_qg = -1;

    #pragma unroll 1
    while (u < u1) {
        const int seg  = u >> 4;          // seg = qg*64 + doc
        const int qg   = seg >> 6;
        const int doc  = seg & 63;
        const int c0   = u & 15;
        const int cend = min(u1 - (seg << 4), CPS);

        const uint4* gsrc = scratch_ps_v + (size_t)doc * TS * U_TOK;

        __syncthreads();   // prior segment's readers done before buf0 overwrite

        // prologue: chunk c0 -> buffer 0
        {
            const uint4* bq = gsrc + (size_t)c0 * SN * U_TOK;
            #pragma unroll
            for (int j = 0; j < 8; j++) {
                int f = j * THREADS + tid;
                int r = f >> 4, cc = f & 15;
                uint32_t dst = sb + r * ROWB + ((cc ^ (r & 7)) << 4);
                asm volatile("cp.async.cg.shared.global [%0], [%1], 16;\n" :: "r"(dst), "l"(bq + f));
            }
            asm volatile("cp.async.commit_group;\n");
        }

        // A fragments (reload only when query group changes)
        if (qg != prev_qg) {
            prev_qg = qg;
            const int rbase = (qg * G_Q + w) * TQ;
            #pragma unroll
            for (int mt = 0; mt < 2; mt++) {
                #pragma unroll
                for (int ks = 0; ks < 8; ks++) {
                    const int r0 = rbase + mt * 16 + g;
                    const int cc = ks * 16 + t * 2;
                    const float2* p0 = reinterpret_cast<const float2*>(qs + (size_t)r0 * DIM + cc);
                    const float2* p1 = reinterpret_cast<const float2*>(qs + (size_t)(r0 + 8) * DIM + cc);
                    float2 v00 = p0[0];
                    float2 v02 = p0[4];
                    float2 v10 = p1[0];
                    float2 v12 = p1[4];
                    Af[mt][ks][0] = pack_h2(v00.x, v00.y);
                    Af[mt][ks][1] = pack_h2(v10.x, v10.y);
                    Af[mt][ks][2] = pack_h2(v02.x, v02.y);
                    Af[mt][ks][3] = pack_h2(v12.x, v12.y);
                }
            }
        }

        float rmax0 = -1e30f, rmax1 = -1e30f, rmax2 = -1e30f, rmax3 = -1e30f;

        #pragma unroll 1
        for (int c = c0; c < cend; c++) {
            const int lc = c - c0;
            asm volatile("cp.async.wait_group 0;\n");
            __syncthreads();

            if (c + 1 < cend) {
                const uint4* gs2  = gsrc + (size_t)(c + 1) * SN * U_TOK;
                uint32_t     dbuf = sb + ((lc + 1) & 1) * BUFB;
                #pragma unroll
                for (int j = 0; j < 8; j++) {
                    int f = j * THREADS + tid;
                    int r = f >> 4, cc = f & 15;
                    uint32_t dst = dbuf + r * ROWB + ((cc ^ (r & 7)) << 4);
                    asm volatile("cp.async.cg.shared.global [%0], [%1], 16;\n" :: "r"(dst), "l"(gs2 + f));
                }
                asm volatile("cp.async.commit_group;\n");
            }

            const uint32_t cbase = sb + (lc & 1) * BUFB + rl * ROWB;
            #pragma unroll
            for (int nf = 0; nf < 8; nf++) {
                float cA[4] = {0.f, 0.f, 0.f, 0.f};
                float cB[4] = {0.f, 0.f, 0.f, 0.f};
                #pragma unroll
                for (int kp = 0; kp < 4; kp++) {
                    uint32_t addr = cbase + nf * 8 * ROWB + ((((kp << 2) | mc) ^ rl) << 4);
                    uint32_t b0, b1, b2, b3;
                    asm volatile("ldmatrix.sync.aligned.m8n8.x4.shared.b16 {%0,%1,%2,%3}, [%4];\n"
                                 : "=r"(b0), "=r"(b1), "=r"(b2), "=r"(b3) : "r"(addr));
                    mma_f16(cA, Af[0][2*kp][0],   Af[0][2*kp][1],   Af[0][2*kp][2],   Af[0][2*kp][3],   b0, b1);
                    mma_f16(cB, Af[1][2*kp][0],   Af[1][2*kp][1],   Af[1][2*kp][2],   Af[1][2*kp][3],   b0, b1);
                    mma_f16(cA, Af[0][2*kp+1][0], Af[0][2*kp+1][1], Af[0][2*kp+1][2], Af[0][2*kp+1][3], b2, b3);
                    mma_f16(cB, Af[1][2*kp+1][0], Af[1][2*kp+1][1], Af[1][2*kp+1][2], Af[1][2*kp+1][3], b2, b3);
                }
                rmax0 = fmaxf(rmax0, fmaxf(cA[0], cA[1]));
                rmax1 = fmaxf(rmax1, fmaxf(cA[2], cA[3]));
                rmax2 = fmaxf(rmax2, fmaxf(cB[0], cB[1]));
                rmax3 = fmaxf(rmax3, fmaxf(cB[2], cB[3]));
            }
        }

        // complete row maxes across the 4 lanes sharing g, then combine globally
        #pragma unroll
        for (int off = 1; off <= 2; off <<= 1) {
            rmax0 = fmaxf(rmax0, __shfl_xor_sync(0xffffffffu, rmax0, off));
            rmax1 = fmaxf(rmax1, __shfl_xor_sync(0xffffffffu, rmax1, off));
            rmax2 = fmaxf(rmax2, __shfl_xor_sync(0xffffffffu, rmax2, off));
            rmax3 = fmaxf(rmax3, __shfl_xor_sync(0xffffffffu, rmax3, off));
        }
        if (t == 0) {
            unsigned* s = g_stage + (size_t)seg * 128 + w * 32;
            atomicMax(&s[g],      enc_f(rmax0));
            atomicMax(&s[g + 8],  enc_f(rmax1));
            atomicMax(&s[g + 16], enc_f(rmax2));
            atomicMax(&s[g + 24], enc_f(rmax3));
        }

        u = (seg << 4) + cend;
    }
}

extern "C" void kernel_launch(void* const* d_in, const int* in_sizes, int n_in,
                              void* d_out, int out_size) {
    const float* qs = (const float*)d_in[0];   // 64*32*128
    const float* ps = (const float*)d_in[1];   // 64*1024*128
    float* out = (float*)d_out;                // 64*64

    cvt_ps_kernel<<<(ND * TS * DIM / 16) / 256, 256>>>((const float4*)ps);
    colbert_kernel<<<NCTA, THREADS>>>(qs);
    final_kernel<<<(NQ * ND * 32) / 256, 256>>>(out);
}